// round 7
// baseline (speedup 1.0000x reference)
#include <cuda_runtime.h>
#include <cuda_fp16.h>
#include <math.h>
#include <stdint.h>

#define N_B   8192
#define N_K   10
#define N_D   128
#define N_QD  256
#define N_KD  384
#define M_HOP2 (N_B * N_K)          // 81920

// ---------------- scratch (static __device__ globals; no allocs) ------------
__device__ float  g_QW   [(size_t)M_HOP2 * 768];     // src @ Wcombq^T + ckq
__device__ __half g_ctx_h[(size_t)M_HOP2 * 768];     // attn-weighted keyv
__device__ __half g_ctx_l[(size_t)M_HOP2 * 768];
__device__ __half g_cat_h[(size_t)M_HOP2 * N_KD];    // [o1 || src] fp16-hi
__device__ __half g_cat_l[(size_t)M_HOP2 * N_KD];
__device__ __half g_h_h  [(size_t)M_HOP2 * N_D];
__device__ __half g_h_l  [(size_t)M_HOP2 * N_D];
__device__ float  g_NL1  [(size_t)M_HOP2 * N_D];
__device__ int    g_inv  [M_HOP2];
__device__ float  g_cq   [2 * N_QD];
// fp16 weights / fp32 combined biases
__device__ __half g_w1  [2*128*384];
__device__ __half g_w2  [2*128*128];
__device__ __half g_wcq [2*768*128];                 // Wk_h^T @ Wq1_h (fp16)
__device__ float  g_ckq [2*768];                     // Wk_h^T @ cq_h
__device__ __half g_wvo [2*256*768];                 // Wo @ Wv_blockdiag (fp16)
__device__ float  g_bvo [2*256];                     // Wo bv + bo
__device__ float  g_wqb [2*2*128];                   // Wq1_h^T bk_h
__device__ float  g_cqb [2*2];                       // bk_h . cq_h

// ---------------- helpers ---------------------------------------------------
__device__ __forceinline__ void split2h(float v, __half& h, __half& l) {
    h = __float2half_rn(v);
    l = __float2half_rn(v - __half2float(h));
}

// ---------------- weight prep ------------------------------------------------
__global__ void prep_weights(const float* __restrict__ W1, const float* __restrict__ W2,
                             __half* __restrict__ w1, __half* __restrict__ w2)
{
    int i = blockIdx.x * blockDim.x + threadIdx.x;
    if (i < 98304) { w1[i] = __float2half_rn(W1[i]); return; }
    i -= 98304;
    if (i < 32768) { w2[i] = __float2half_rn(W2[i]); }
}

// cq[j] = bq[j] + sum_t cos(tb[t]) * Wq[j,128+t]   (fp32, exact path)
__global__ void const_q_kernel(const float* __restrict__ Wq,
                               const float* __restrict__ bq,
                               const float* __restrict__ tb,
                               float* __restrict__ cq)
{
    __shared__ float ct[128];
    int p = blockIdx.x, j = threadIdx.x;
    if (j < 128) ct[j] = cosf(tb[j]);
    __syncthreads();
    const float* W = Wq + (size_t)p * N_QD * N_QD;
    float s = bq[p * N_QD + j];
    #pragma unroll 4
    for (int t = 0; t < 128; t++) s = fmaf(ct[t], W[(size_t)j * N_QD + 128 + t], s);
    cq[p * N_QD + j] = s;
}

// Wcombq[p][h*384+j, s] = sum_d Wk[p][h*128+d, j] * Wq[p][h*128+d, s]
// ckq[p][h*384+j]       = sum_d Wk[p][h*128+d, j] * cq[p][h*128+d]
__global__ void comb_q_kernel(const float* __restrict__ Wk, const float* __restrict__ Wq,
                              const float* __restrict__ cq,
                              __half* __restrict__ wcq, float* __restrict__ ckq)
{
    __shared__ float wk[128];
    int jr = blockIdx.x;              // 0..767
    int p = blockIdx.y, s = threadIdx.x;
    int h = jr / 384, j = jr % 384;
    wk[s] = Wk[((size_t)p*256 + h*128 + s)*384 + j];
    __syncthreads();
    float acc = 0.f;
    #pragma unroll 4
    for (int d = 0; d < 128; d++)
        acc = fmaf(wk[d], Wq[((size_t)p*256 + h*128 + d)*256 + s], acc);
    wcq[((size_t)p*768 + jr)*128 + s] = __float2half_rn(acc);
    if (s == 0) {
        float c = 0.f;
        for (int d = 0; d < 128; d++) c = fmaf(wk[d], cq[p*256 + h*128 + d], c);
        ckq[p*768 + jr] = c;
    }
}

// wqb[p][h][s] = sum_d Wq[p][h*128+d, s] * bk[p][h*128+d];  cqb = bk_h . cq_h
__global__ void comb_qb_kernel(const float* __restrict__ Wq, const float* __restrict__ bk,
                               const float* __restrict__ cq,
                               float* __restrict__ wqb, float* __restrict__ cqb)
{
    int h = blockIdx.x, p = blockIdx.y, s = threadIdx.x;
    float acc = 0.f;
    #pragma unroll 4
    for (int d = 0; d < 128; d++)
        acc = fmaf(Wq[((size_t)p*256 + h*128 + d)*256 + s], bk[p*256 + h*128 + d], acc);
    wqb[(p*2 + h)*128 + s] = acc;
    if (s == 0) {
        float c = 0.f;
        for (int d = 0; d < 128; d++) c = fmaf(bk[p*256 + h*128 + d], cq[p*256 + h*128 + d], c);
        cqb[p*2 + h] = c;
    }
}

// WcombVO[p][i, h*384+j'] = sum_d Wo[p][i, h*128+d] * Wv[p][h*128+d, j']
// bvo[p][i] = bo[p][i] + sum_e Wo[p][i, e] * bv[p][e]
__global__ void comb_vo_kernel(const float* __restrict__ Wo, const float* __restrict__ Wv,
                               const float* __restrict__ bo, const float* __restrict__ bv,
                               __half* __restrict__ wvo, float* __restrict__ bvo)
{
    int i = blockIdx.x, p = blockIdx.y, j = threadIdx.x;   // j in 0..767
    int h = j / 384, jp = j % 384;
    float acc = 0.f;
    #pragma unroll 4
    for (int d = 0; d < 128; d++)
        acc = fmaf(Wo[((size_t)p*256 + i)*256 + h*128 + d],
                   Wv[((size_t)p*256 + h*128 + d)*384 + jp], acc);
    wvo[((size_t)p*256 + i)*768 + j] = __float2half_rn(acc);
    if (j == 0) {
        float c = bo[p*256 + i];
        for (int e = 0; e < 256; e++)
            c = fmaf(Wo[((size_t)p*256 + i)*256 + e], bv[p*256 + e], c);
        bvo[p*256 + i] = c;
    }
}

// gather emb0 into cat buffer at col 256 (ld = 384)
__global__ void gather_emb_kernel(const float* __restrict__ nf,
                                  const float* __restrict__ mem,
                                  const int* __restrict__ idx,
                                  __half* __restrict__ dh, __half* __restrict__ dl, int n)
{
    int r = blockIdx.x;
    if (r >= n) return;
    int t = threadIdx.x;
    size_t s = (size_t)idx[r] * N_D + t;
    float v = nf[s] + mem[s];
    size_t o = (size_t)r * N_KD + 256 + t;
    split2h(v, dh[o], dl[o]);
}

// ---------------- fp16 2-pass tensor-core GEMM ------------------------------
#define GF_RELU 1
#define SMS  40
#define MATB (128 * SMS * 2)
#define STGB (3 * MATB)
#define NSTG 3
#define GSMEM (NSTG * STGB)

__device__ __forceinline__ void cpa16(uint32_t s, const void* g) {
    asm volatile("cp.async.cg.shared.global [%0], [%1], 16;\n" :: "r"(s), "l"(g));
}
__device__ __forceinline__ void ldm4(uint32_t* r, uint32_t a) {
    asm volatile("ldmatrix.sync.aligned.m8n8.x4.shared.b16 {%0,%1,%2,%3},[%4];\n"
                 : "=r"(r[0]), "=r"(r[1]), "=r"(r[2]), "=r"(r[3]) : "r"(a));
}
__device__ __forceinline__ void mmaf16(float* d, const uint32_t* a, uint32_t b0, uint32_t b1) {
    asm volatile("mma.sync.aligned.m16n8k16.row.col.f32.f16.f16.f32 "
                 "{%0,%1,%2,%3},{%4,%5,%6,%7},{%8,%9},{%0,%1,%2,%3};\n"
                 : "+f"(d[0]), "+f"(d[1]), "+f"(d[2]), "+f"(d[3])
                 : "r"(a[0]), "r"(a[1]), "r"(a[2]), "r"(a[3]), "r"(b0), "r"(b1));
}

__device__ __forceinline__ void issue_chunk(uint32_t sw, uint32_t bufofs,
    const __half* Ah, const __half* Al, size_t ga,
    const __half* Wh, size_t gw)
{
    uint32_t s0 = sw + bufofs;
    cpa16(s0,          Ah + ga); cpa16(s0 + 32,          Ah + ga + 16);
    cpa16(s0 + MATB,   Al + ga); cpa16(s0 + MATB + 32,   Al + ga + 16);
    cpa16(s0 + 2*MATB, Wh + gw); cpa16(s0 + 2*MATB + 32, Wh + gw + 16);
    asm volatile("cp.async.commit_group;\n");
}

__global__ __launch_bounds__(256, 2) void mma_gemm(
    const __half* __restrict__ Ah, const __half* __restrict__ Al, int lda,
    const __half* __restrict__ Wh, int ldw,
    int Kd,
    const float* __restrict__ bias,
    float* __restrict__ Cf, int ldcf,
    __half* __restrict__ Oh, __half* __restrict__ Ol, int ldo,
    const int* __restrict__ zmask, int flags)
{
    extern __shared__ __align__(16) char smem_raw[];
    uint32_t sb = (uint32_t)__cvta_generic_to_shared(smem_raw);
    int tid = threadIdx.x;
    int m0 = blockIdx.y * 128, n0 = blockIdx.x * 128;
    int lane = tid & 31, wid = tid >> 5;
    int wm = wid & 1, wn = wid >> 1;

    float d[4][4][4];
    #pragma unroll
    for (int i = 0; i < 4; i++)
        #pragma unroll
        for (int j = 0; j < 4; j++)
            #pragma unroll
            for (int r = 0; r < 4; r++) d[i][j][r] = 0.f;

    int row = tid >> 1;
    int ce  = (tid & 1) << 3;
    size_t ga0 = (size_t)(m0 + row) * lda + ce;
    size_t gw0 = (size_t)(n0 + row) * ldw + ce;
    uint32_t sw = sb + (uint32_t)(row * SMS + ce) * 2;

    int nch = Kd >> 5;
    issue_chunk(sw, 0, Ah, Al, ga0, Wh, gw0);
    if (nch > 1) issue_chunk(sw, STGB, Ah, Al, ga0 + 32, Wh, gw0 + 32);

    for (int c = 0; c < nch; c++) {
        if (c + 2 < nch) {
            int k0 = (c + 2) << 5;
            issue_chunk(sw, (uint32_t)((c + 2) % NSTG) * STGB, Ah, Al, ga0 + k0, Wh, gw0 + k0);
        }
        int issuedJ = (c + 2 < nch) ? c + 2 : nch - 1;
        int allow = issuedJ - c;
        if (allow >= 2)      asm volatile("cp.async.wait_group 2;\n" ::: "memory");
        else if (allow == 1) asm volatile("cp.async.wait_group 1;\n" ::: "memory");
        else                 asm volatile("cp.async.wait_group 0;\n" ::: "memory");
        __syncthreads();

        uint32_t base = sb + (uint32_t)(c % NSTG) * STGB;
        #pragma unroll
        for (int h = 0; h < 2; h++) {
            uint32_t ah[4][4], al[4][4], bh[2][4];
            int colA = (h << 4) + ((lane >> 4) << 3);
            #pragma unroll
            for (int mi = 0; mi < 4; mi++) {
                int r_ = wm * 64 + mi * 16 + (lane & 15);
                uint32_t ad = base + (uint32_t)(r_ * SMS + colA) * 2;
                ldm4(ah[mi], ad);
                ldm4(al[mi], ad + MATB);
            }
            #pragma unroll
            for (int nj2 = 0; nj2 < 2; nj2++) {
                int r_ = wn * 32 + nj2 * 16 + (lane & 7) + (((lane >> 3) & 1) << 3);
                uint32_t bd = base + 2 * MATB + (uint32_t)(r_ * SMS + colA) * 2;
                ldm4(bh[nj2], bd);
            }
            #pragma unroll
            for (int mi = 0; mi < 4; mi++)
                #pragma unroll
                for (int nj = 0; nj < 4; nj++)
                    mmaf16(d[mi][nj], ah[mi], bh[nj >> 1][nj & 1], bh[nj >> 1][(nj & 1) + 2]);
            #pragma unroll
            for (int mi = 0; mi < 4; mi++)
                #pragma unroll
                for (int nj = 0; nj < 4; nj++)
                    mmaf16(d[mi][nj], al[mi], bh[nj >> 1][nj & 1], bh[nj >> 1][(nj & 1) + 2]);
        }
        __syncthreads();
    }

    int gr = lane >> 2, tg = lane & 3;
    #pragma unroll
    for (int mi = 0; mi < 4; mi++) {
        int mb = m0 + wm * 64 + mi * 16 + gr;
        #pragma unroll
        for (int half = 0; half < 2; half++) {
            int m = mb + half * 8;
            bool zero = (zmask != nullptr) && (zmask[m] != 0);
            #pragma unroll
            for (int nj = 0; nj < 4; nj++) {
                int n = n0 + wn * 32 + nj * 8 + tg * 2;
                float v0 = d[mi][nj][half * 2 + 0];
                float v1 = d[mi][nj][half * 2 + 1];
                if (bias) { v0 += bias[n]; v1 += bias[n + 1]; }
                if (flags & GF_RELU) { v0 = fmaxf(v0, 0.f); v1 = fmaxf(v1, 0.f); }
                if (zero) { v0 = 0.f; v1 = 0.f; }
                if (Cf) *(float2*)&Cf[(size_t)m * ldcf + n] = make_float2(v0, v1);
                if (Oh) {
                    __half2 hh, ll;
                    split2h(v0, hh.x, ll.x);
                    split2h(v1, hh.y, ll.y);
                    *(__half2*)&Oh[(size_t)m * ldo + n] = hh;
                    *(__half2*)&Ol[(size_t)m * ldo + n] = ll;
                }
            }
        }
    }
}

// ---------------- fused keyv-build + attention (smem keyv) ------------------
// One warp per row m (2 warps/block). Pass A builds keyv rows in fp32 into
// smem + computes scores; pass B reads smem for ctx. qb computed from src.
__global__ __launch_bounds__(64) void fused_attn(
    const int* __restrict__ neigh,
    const int* __restrict__ eidx,
    const float* __restrict__ etime,
    const float* __restrict__ ts, int ts_div,
    const float* __restrict__ nf, const float* __restrict__ mem,
    const float* __restrict__ ef,
    const float* __restrict__ dense_neigh,
    const float* __restrict__ tw, const float* __restrict__ tb,
    const float* __restrict__ QW,
    const __half* __restrict__ cath, const __half* __restrict__ catl,
    const float* __restrict__ wqb, const float* __restrict__ cqb,  // +p offsets
    __half* __restrict__ ctxh, __half* __restrict__ ctxl,
    int* __restrict__ inv, int M)
{
    __shared__ float s_tw[128], s_tb[128];
    __shared__ float kv[2][N_K][384];
    int tid = threadIdx.x;
    s_tw[tid] = tw[tid];       s_tb[tid] = tb[tid];
    s_tw[tid + 64] = tw[tid + 64]; s_tb[tid + 64] = tb[tid + 64];
    __syncthreads();

    int wl = tid >> 5, lane = tid & 31;
    int m = blockIdx.x * 2 + wl;
    if (m >= M) return;
    const float SC = 0.08838834764831843f;   // 1/sqrt(128)
    int jj = 2 * lane;

    // qb_h = src . wqb_h + cqb_h   (src = cat hi+lo cols 256..383)
    float qb0, qb1;
    {
        size_t sbse = (size_t)m * N_KD + 256 + jj;
        float2 sh0 = __half22float2(*(const __half2*)&cath[sbse]);
        float2 sl0 = __half22float2(*(const __half2*)&catl[sbse]);
        float2 sh1 = __half22float2(*(const __half2*)&cath[sbse + 64]);
        float2 sl1 = __half22float2(*(const __half2*)&catl[sbse + 64]);
        float sx0 = sh0.x + sl0.x, sy0 = sh0.y + sl0.y;
        float sx1 = sh1.x + sl1.x, sy1 = sh1.y + sl1.y;
        float2 w00 = *(const float2*)&wqb[jj],       w01 = *(const float2*)&wqb[jj + 64];
        float2 w10 = *(const float2*)&wqb[128 + jj], w11 = *(const float2*)&wqb[128 + jj + 64];
        qb0 = sx0*w00.x + sy0*w00.y + sx1*w01.x + sy1*w01.y;
        qb1 = sx0*w10.x + sy0*w10.y + sx1*w11.x + sy1*w11.y;
        #pragma unroll
        for (int o = 16; o; o >>= 1) {
            qb0 += __shfl_xor_sync(0xffffffffu, qb0, o);
            qb1 += __shfl_xor_sync(0xffffffffu, qb1, o);
        }
        qb0 += cqb[0]; qb1 += cqb[1];
    }

    float2 qw0[6], qw1[6];
    {
        const float* qwp = QW + (size_t)m * 768;
        #pragma unroll
        for (int t = 0; t < 6; t++) {
            qw0[t] = *(const float2*)&qwp[jj + 64 * t];
            qw1[t] = *(const float2*)&qwp[384 + jj + 64 * t];
        }
    }

    float tsv = ts[m / ts_div];
    bool msk[N_K]; bool allm = true;
    int nd[N_K], ed[N_K];
    #pragma unroll
    for (int k = 0; k < N_K; k++) {
        nd[k] = neigh[m * N_K + k];
        ed[k] = eidx [m * N_K + k];
        msk[k] = (nd[k] == 0);
        allm = allm && msk[k];
    }

    // ---- pass A: build keyv into smem + scores
    float s0[N_K], s1[N_K];
    #pragma unroll
    for (int k = 0; k < N_K; k++) {
        float2 v[6];
        if (dense_neigh) {
            const float* dr = dense_neigh + (size_t)(m * N_K + k) * N_D;
            v[0] = *(const float2*)&dr[jj];
            v[1] = *(const float2*)&dr[jj + 64];
        } else {
            const float* nr = nf  + (size_t)nd[k] * N_D;
            const float* mr = mem + (size_t)nd[k] * N_D;
            float2 a0 = *(const float2*)&nr[jj],      b0 = *(const float2*)&mr[jj];
            float2 a1 = *(const float2*)&nr[jj + 64], b1 = *(const float2*)&mr[jj + 64];
            v[0] = make_float2(a0.x + b0.x, a0.y + b0.y);
            v[1] = make_float2(a1.x + b1.x, a1.y + b1.y);
        }
        {
            const float* er = ef + (size_t)ed[k] * N_D;
            v[2] = *(const float2*)&er[jj];
            v[3] = *(const float2*)&er[jj + 64];
        }
        float dd = tsv - etime[m * N_K + k];
        v[4].x = cosf(__fadd_rn(__fmul_rn(dd, s_tw[jj]),      s_tb[jj]));
        v[4].y = cosf(__fadd_rn(__fmul_rn(dd, s_tw[jj + 1]),  s_tb[jj + 1]));
        v[5].x = cosf(__fadd_rn(__fmul_rn(dd, s_tw[jj + 64]), s_tb[jj + 64]));
        v[5].y = cosf(__fadd_rn(__fmul_rn(dd, s_tw[jj + 65]), s_tb[jj + 65]));
        float p0 = 0.f, p1 = 0.f;
        #pragma unroll
        for (int t = 0; t < 6; t++) {
            *(float2*)&kv[wl][k][jj + 64 * t] = v[t];
            p0 += qw0[t].x * v[t].x + qw0[t].y * v[t].y;
            p1 += qw1[t].x * v[t].x + qw1[t].y * v[t].y;
        }
        #pragma unroll
        for (int o = 16; o; o >>= 1) {
            p0 += __shfl_xor_sync(0xffffffffu, p0, o);
            p1 += __shfl_xor_sync(0xffffffffu, p1, o);
        }
        bool mk = msk[k] && !(allm && k == 0);
        s0[k] = mk ? -1e9f : (p0 + qb0) * SC;
        s1[k] = mk ? -1e9f : (p1 + qb1) * SC;
    }

    float mx0 = s0[0], mx1 = s1[0];
    #pragma unroll
    for (int k = 1; k < N_K; k++) { mx0 = fmaxf(mx0, s0[k]); mx1 = fmaxf(mx1, s1[k]); }
    float sm0 = 0.f, sm1 = 0.f;
    #pragma unroll
    for (int k = 0; k < N_K; k++) {
        s0[k] = expf(s0[k] - mx0); sm0 += s0[k];
        s1[k] = expf(s1[k] - mx1); sm1 += s1[k];
    }
    float r0 = 1.f / sm0, r1 = 1.f / sm1;

    // ---- pass B: ctx from smem keyv
    float2 a0[6], a1[6];
    #pragma unroll
    for (int t = 0; t < 6; t++) { a0[t] = make_float2(0.f, 0.f); a1[t] = make_float2(0.f, 0.f); }
    #pragma unroll
    for (int k = 0; k < N_K; k++) {
        float w0 = s0[k] * r0, w1 = s1[k] * r1;
        #pragma unroll
        for (int t = 0; t < 6; t++) {
            float2 v = *(const float2*)&kv[wl][k][jj + 64 * t];
            a0[t].x = fmaf(w0, v.x, a0[t].x); a0[t].y = fmaf(w0, v.y, a0[t].y);
            a1[t].x = fmaf(w1, v.x, a1[t].x); a1[t].y = fmaf(w1, v.y, a1[t].y);
        }
    }

    size_t ob = (size_t)m * 768 + jj;
    #pragma unroll
    for (int t = 0; t < 6; t++) {
        __half2 hh, ll;
        split2h(a0[t].x, hh.x, ll.x); split2h(a0[t].y, hh.y, ll.y);
        *(__half2*)&ctxh[ob + 64 * t] = hh;
        *(__half2*)&ctxl[ob + 64 * t] = ll;
        split2h(a1[t].x, hh.x, ll.x); split2h(a1[t].y, hh.y, ll.y);
        *(__half2*)&ctxh[ob + 384 + 64 * t] = hh;
        *(__half2*)&ctxl[ob + 384 + 64 * t] = ll;
    }
    if (lane == 0) inv[m] = allm ? 1 : 0;
}

// ---------------- one temporal attention layer ------------------------------
struct Ptrs {
    __half *ctxh, *ctxl, *cath, *catl, *hh, *hl;
    float *QW; int* inv;
    __half *w1, *w2, *wcq, *wvo;
    float *cq, *ckq, *bvo, *wqb, *cqb;
};

static void run_layer(const Ptrs& P, int p, int M,
                      const int* neigh, const float* dense_neigh,
                      const int* eidx, const float* etime,
                      const float* ts, int ts_div,
                      const float* nf, const float* mem, const float* ef,
                      const float* tw, const float* tb,
                      const float* b1, const float* b2,
                      float* outCf, __half* outOh, __half* outOl, int out_ldo)
{
    // QW = src @ Wcombq^T + ckq
    mma_gemm<<<dim3(6, M/128), 256, GSMEM>>>(
        P.cath + 256, P.catl + 256, 384,
        P.wcq + (size_t)p*768*128, 128, 128,
        P.ckq + p*768, P.QW, 768, nullptr, nullptr, 0, nullptr, 0);
    // fused keyv-build + attention
    fused_attn<<<(M + 1) / 2, 64>>>(neigh, eidx, etime, ts, ts_div,
                                    nf, mem, ef, dense_neigh, tw, tb,
                                    P.QW, P.cath, P.catl,
                                    P.wqb + p*256, P.cqb + p*2,
                                    P.ctxh, P.ctxl, P.inv, M);
    // o1 = ctx @ WcombVO^T + bvo  (zeroed on invalid rows) -> cat cols 0..255
    mma_gemm<<<dim3(2, M/128), 256, GSMEM>>>(
        P.ctxh, P.ctxl, 768,
        P.wvo + (size_t)p*256*768, 768, 768,
        P.bvo + p*256, nullptr, 0, P.cath, P.catl, 384, P.inv, 0);
    // h = relu(cat @ W1^T + b1)
    mma_gemm<<<dim3(1, M/128), 256, GSMEM>>>(
        P.cath, P.catl, 384,
        P.w1 + (size_t)p*49152, 384, 384,
        b1 + p*128, nullptr, 0, P.hh, P.hl, 128, nullptr, GF_RELU);
    // out = h @ W2^T + b2
    mma_gemm<<<dim3(1, M/128), 256, GSMEM>>>(
        P.hh, P.hl, 128,
        P.w2 + (size_t)p*16384, 128, 128,
        b2 + p*128, outCf, 128, outOh, outOl, out_ldo, nullptr, 0);
}

// ---------------- entry -----------------------------------------------------
extern "C" void kernel_launch(void* const* d_in, const int* in_sizes, int n_in,
                              void* d_out, int out_size)
{
    const float* node_feat   = (const float*)d_in[0];
    const float* memory      = (const float*)d_in[1];
    const float* edge_feat   = (const float*)d_in[2];
    const float* time_w      = (const float*)d_in[3];
    const float* time_b      = (const float*)d_in[4];
    const float* Wq          = (const float*)d_in[5];
    const float* bq          = (const float*)d_in[6];
    const float* Wk          = (const float*)d_in[7];
    const float* bk          = (const float*)d_in[8];
    const float* Wv          = (const float*)d_in[9];
    const float* bv          = (const float*)d_in[10];
    const float* Wo          = (const float*)d_in[11];
    const float* bo          = (const float*)d_in[12];
    const float* W1          = (const float*)d_in[13];
    const float* b1          = (const float*)d_in[14];
    const float* W2          = (const float*)d_in[15];
    const float* b2          = (const float*)d_in[16];
    const float* timestamps  = (const float*)d_in[17];
    const int*   src_nodes   = (const int*)d_in[18];
    const int*   neighbors1  = (const int*)d_in[19];
    const int*   edge_idx1   = (const int*)d_in[20];
    const float* edge_times1 = (const float*)d_in[21];
    const int*   neighbors2  = (const int*)d_in[22];
    const int*   edge_idx2   = (const int*)d_in[23];
    const float* edge_times2 = (const float*)d_in[24];

    cudaFuncSetAttribute(mma_gemm, cudaFuncAttributeMaxDynamicSharedMemorySize, GSMEM);

    Ptrs P; float* NL1;
    cudaGetSymbolAddress((void**)&P.QW,   g_QW);
    cudaGetSymbolAddress((void**)&P.ctxh, g_ctx_h);
    cudaGetSymbolAddress((void**)&P.ctxl, g_ctx_l);
    cudaGetSymbolAddress((void**)&P.cath, g_cat_h);
    cudaGetSymbolAddress((void**)&P.catl, g_cat_l);
    cudaGetSymbolAddress((void**)&P.hh,   g_h_h);
    cudaGetSymbolAddress((void**)&P.hl,   g_h_l);
    cudaGetSymbolAddress((void**)&NL1,    g_NL1);
    cudaGetSymbolAddress((void**)&P.inv,  g_inv);
    cudaGetSymbolAddress((void**)&P.cq,   g_cq);
    cudaGetSymbolAddress((void**)&P.w1,   g_w1);
    cudaGetSymbolAddress((void**)&P.w2,   g_w2);
    cudaGetSymbolAddress((void**)&P.wcq,  g_wcq);
    cudaGetSymbolAddress((void**)&P.ckq,  g_ckq);
    cudaGetSymbolAddress((void**)&P.wvo,  g_wvo);
    cudaGetSymbolAddress((void**)&P.bvo,  g_bvo);
    cudaGetSymbolAddress((void**)&P.wqb,  g_wqb);
    cudaGetSymbolAddress((void**)&P.cqb,  g_cqb);

    // weight prep (serialized on stream; ~tens of µs total)
    prep_weights<<<512, 256>>>(W1, W2, P.w1, P.w2);
    const_q_kernel<<<2, 256>>>(Wq, bq, time_b, P.cq);
    comb_q_kernel <<<dim3(768, 2), 128>>>(Wk, Wq, P.cq, P.wcq, P.ckq);
    comb_qb_kernel<<<dim3(2, 2),   128>>>(Wq, bk, P.cq, P.wqb, P.cqb);
    comb_vo_kernel<<<dim3(256, 2), 768>>>(Wo, Wv, bo, bv, P.wvo, P.bvo);

    // stage 1: layer-1 embedding of flattened first-hop neighbors (p0)
    gather_emb_kernel<<<M_HOP2, 128>>>(node_feat, memory, neighbors1, P.cath, P.catl, M_HOP2);
    run_layer(P, 0, M_HOP2, neighbors2, nullptr, edge_idx2, edge_times2,
              timestamps, N_K, node_feat, memory, edge_feat, time_w, time_b,
              b1, b2, NL1, nullptr, nullptr, 0);

    // stage 2: layer-1 embedding of src nodes (p0); SL1 -> cat col 256
    gather_emb_kernel<<<N_B, 128>>>(node_feat, memory, src_nodes, P.cath, P.catl, N_B);
    run_layer(P, 0, N_B, neighbors1, nullptr, edge_idx1, edge_times1,
              timestamps, 1, node_feat, memory, edge_feat, time_w, time_b,
              b1, b2, nullptr, P.cath + 256, P.catl + 256, 384);

    // stage 3: layer-2 aggregation (p1), neighbor feats = NL1
    run_layer(P, 1, N_B, neighbors1, NL1, edge_idx1, edge_times1,
              timestamps, 1, node_feat, memory, edge_feat, time_w, time_b,
              b1, b2, (float*)d_out, nullptr, nullptr, 0);
}

// round 9
// speedup vs baseline: 1.2427x; 1.2427x over previous
#include <cuda_runtime.h>
#include <cuda_fp16.h>
#include <math.h>
#include <stdint.h>

#define N_B   8192
#define N_K   10
#define N_D   128
#define N_QD  256
#define N_KD  384
#define M_HOP2 (N_B * N_K)          // 81920

// ---------------- scratch (static __device__ globals; no allocs) ------------
__device__ float  g_QW   [(size_t)M_HOP2 * 768];     // src @ Wcombq^T + ckq
__device__ __half g_buf_h[(size_t)M_HOP2 * 896];     // [ctx(768) || src(128)] hi
__device__ __half g_buf_l[(size_t)M_HOP2 * 896];     // lo
__device__ __half g_h_h  [(size_t)M_HOP2 * N_D];
__device__ __half g_h_l  [(size_t)M_HOP2 * N_D];
__device__ float  g_NL1  [(size_t)M_HOP2 * N_D];
__device__ int    g_inv  [M_HOP2];
__device__ float  g_cq   [2 * N_QD];
// combined weights
__device__ __half g_wcq [2*768*128];                 // Wk_h^T @ Wq1_h
__device__ float  g_ckq [2*768];                     // Wk_h^T @ cq_h
__device__ float  g_tmpvo[2*256*768];                // Wo @ Wv_blockdiag (fp32 temp)
__device__ float  g_bvo [2*256];                     // Wo bv + bo
__device__ __half g_wf  [2*128*896];                 // [W1a@Wvo || W1b] fp16
__device__ float  g_cvec[2*128];                     // W1a @ bvo
__device__ __half g_w2  [2*128*128];
__device__ float  g_wqb [2*2*128];                   // Wq1_h^T bk_h
__device__ float  g_cqb [2*2];                       // bk_h . cq_h

// ---------------- helpers ---------------------------------------------------
__device__ __forceinline__ void split2h(float v, __half& h, __half& l) {
    h = __float2half_rn(v);
    l = __float2half_rn(v - __half2float(h));
}

// ---------------- prep kernels ----------------------------------------------
// cq[j] = bq[j] + sum_t cos(tb[t]) * Wq[j,128+t]
__global__ void const_q_kernel(const float* __restrict__ Wq,
                               const float* __restrict__ bq,
                               const float* __restrict__ tb,
                               float* __restrict__ cq)
{
    __shared__ float ct[128];
    int p = blockIdx.x, j = threadIdx.x;
    if (j < 128) ct[j] = cosf(tb[j]);
    __syncthreads();
    const float* W = Wq + (size_t)p * N_QD * N_QD;
    float s = bq[p * N_QD + j];
    #pragma unroll 4
    for (int t = 0; t < 128; t++) s = fmaf(ct[t], W[(size_t)j * N_QD + 128 + t], s);
    cq[p * N_QD + j] = s;
}

// Wcombq[p][h*384+j, s] = sum_d Wk[p][h*128+d, j] * Wq[p][h*128+d, s]
// ckq[p][h*384+j]       = sum_d Wk[p][h*128+d, j] * cq[p][h*128+d]
__global__ void comb_q_kernel(const float* __restrict__ Wk, const float* __restrict__ Wq,
                              const float* __restrict__ cq,
                              __half* __restrict__ wcq, float* __restrict__ ckq)
{
    __shared__ float wk[128];
    int jr = blockIdx.x, p = blockIdx.y, s = threadIdx.x;
    int h = jr / 384, j = jr % 384;
    wk[s] = Wk[((size_t)p*256 + h*128 + s)*384 + j];
    __syncthreads();
    float acc = 0.f;
    #pragma unroll 4
    for (int d = 0; d < 128; d++)
        acc = fmaf(wk[d], Wq[((size_t)p*256 + h*128 + d)*256 + s], acc);
    wcq[((size_t)p*768 + jr)*128 + s] = __float2half_rn(acc);
    if (s == 0) {
        float c = 0.f;
        for (int d = 0; d < 128; d++) c = fmaf(wk[d], cq[p*256 + h*128 + d], c);
        ckq[p*768 + jr] = c;
    }
}

// wqb[p][h][s] = sum_d Wq[p][h*128+d, s] * bk[p][h*128+d];  cqb = bk_h . cq_h
__global__ void comb_qb_kernel(const float* __restrict__ Wq, const float* __restrict__ bk,
                               const float* __restrict__ cq,
                               float* __restrict__ wqb, float* __restrict__ cqb)
{
    int h = blockIdx.x, p = blockIdx.y, s = threadIdx.x;
    float acc = 0.f;
    #pragma unroll 4
    for (int d = 0; d < 128; d++)
        acc = fmaf(Wq[((size_t)p*256 + h*128 + d)*256 + s], bk[p*256 + h*128 + d], acc);
    wqb[(p*2 + h)*128 + s] = acc;
    if (s == 0) {
        float c = 0.f;
        for (int d = 0; d < 128; d++) c = fmaf(bk[p*256 + h*128 + d], cq[p*256 + h*128 + d], c);
        cqb[p*2 + h] = c;
    }
}

// tmpvo[p][i, h*384+j'] = sum_d Wo[p][i, h*128+d] * Wv[p][h*128+d, j']  (fp32)
// bvo[p][i] = bo[p][i] + sum_e Wo[p][i, e] * bv[p][e]
__global__ void comb_vo_kernel(const float* __restrict__ Wo, const float* __restrict__ Wv,
                               const float* __restrict__ bo, const float* __restrict__ bv,
                               float* __restrict__ tmpvo, float* __restrict__ bvo)
{
    int i = blockIdx.x, p = blockIdx.y, j = threadIdx.x;   // j 0..767
    int h = j / 384, jp = j % 384;
    float acc = 0.f;
    #pragma unroll 4
    for (int d = 0; d < 128; d++)
        acc = fmaf(Wo[((size_t)p*256 + i)*256 + h*128 + d],
                   Wv[((size_t)p*256 + h*128 + d)*384 + jp], acc);
    tmpvo[((size_t)p*256 + i)*768 + j] = acc;
    if (j == 0) {
        float c = bo[p*256 + i];
        for (int e = 0; e < 256; e++)
            c = fmaf(Wo[((size_t)p*256 + i)*256 + e], bv[p*256 + e], c);
        bvo[p*256 + i] = c;
    }
}

// wf[p][n, j<768] = fp16(sum_e W1[p][n,e] * tmpvo[p][e,j]);  cvec[n]=W1a.bvo
__global__ void comb_w1_kernel(const float* __restrict__ W1, const float* __restrict__ tmpvo,
                               const float* __restrict__ bvo,
                               __half* __restrict__ wf, float* __restrict__ cvec)
{
    __shared__ float w1r[256];
    int n = blockIdx.x, p = blockIdx.y, j = threadIdx.x;  // j 0..767
    if (j < 256) w1r[j] = W1[((size_t)p*128 + n)*384 + j];
    __syncthreads();
    float acc = 0.f;
    #pragma unroll 4
    for (int e = 0; e < 256; e++)
        acc = fmaf(w1r[e], tmpvo[((size_t)p*256 + e)*768 + j], acc);
    wf[((size_t)p*128 + n)*896 + j] = __float2half_rn(acc);
    if (j == 0) {
        float c = 0.f;
        for (int e = 0; e < 256; e++) c = fmaf(w1r[e], bvo[p*256 + e], c);
        cvec[p*128 + n] = c;
    }
}

// copy W1b into wf cols 768..895 + convert W2
__global__ void prep_misc(const float* __restrict__ W1, const float* __restrict__ W2,
                          __half* __restrict__ wf, __half* __restrict__ w2)
{
    int i = blockIdx.x * blockDim.x + threadIdx.x;
    if (i < 2*128*128) {
        int p = i >> 14, r = i & 16383;
        int n = r >> 7, d = r & 127;
        wf[((size_t)p*128 + n)*896 + 768 + d] =
            __float2half_rn(W1[((size_t)p*128 + n)*384 + 256 + d]);
        return;
    }
    i -= 2*128*128;
    if (i < 2*128*128) w2[i] = __float2half_rn(W2[i]);
}

// gather emb0 into buf at col 768 (ld = 896)
__global__ void gather_emb_kernel(const float* __restrict__ nf,
                                  const float* __restrict__ mem,
                                  const int* __restrict__ idx,
                                  __half* __restrict__ dh, __half* __restrict__ dl, int n)
{
    int r = blockIdx.x;
    if (r >= n) return;
    int t = threadIdx.x;
    size_t s = (size_t)idx[r] * N_D + t;
    float v = nf[s] + mem[s];
    size_t o = (size_t)r * 896 + 768 + t;
    split2h(v, dh[o], dl[o]);
}

// ---------------- fp16 2-pass tensor-core GEMM ------------------------------
#define GF_RELU 1
#define SMS  40
#define MATB (128 * SMS * 2)
#define STGB (3 * MATB)
#define NSTG 3
#define GSMEM (NSTG * STGB)

__device__ __forceinline__ void cpa16(uint32_t s, const void* g) {
    asm volatile("cp.async.cg.shared.global [%0], [%1], 16;\n" :: "r"(s), "l"(g));
}
__device__ __forceinline__ void ldm4(uint32_t* r, uint32_t a) {
    asm volatile("ldmatrix.sync.aligned.m8n8.x4.shared.b16 {%0,%1,%2,%3},[%4];\n"
                 : "=r"(r[0]), "=r"(r[1]), "=r"(r[2]), "=r"(r[3]) : "r"(a));
}
__device__ __forceinline__ void mmaf16(float* d, const uint32_t* a, uint32_t b0, uint32_t b1) {
    asm volatile("mma.sync.aligned.m16n8k16.row.col.f32.f16.f16.f32 "
                 "{%0,%1,%2,%3},{%4,%5,%6,%7},{%8,%9},{%0,%1,%2,%3};\n"
                 : "+f"(d[0]), "+f"(d[1]), "+f"(d[2]), "+f"(d[3])
                 : "r"(a[0]), "r"(a[1]), "r"(a[2]), "r"(a[3]), "r"(b0), "r"(b1));
}

__device__ __forceinline__ void issue_chunk(uint32_t sw, uint32_t bufofs,
    const __half* Ah, const __half* Al, size_t ga,
    const __half* Wh, size_t gw)
{
    uint32_t s0 = sw + bufofs;
    cpa16(s0,          Ah + ga); cpa16(s0 + 32,          Ah + ga + 16);
    cpa16(s0 + MATB,   Al + ga); cpa16(s0 + MATB + 32,   Al + ga + 16);
    cpa16(s0 + 2*MATB, Wh + gw); cpa16(s0 + 2*MATB + 32, Wh + gw + 16);
    asm volatile("cp.async.commit_group;\n");
}

// epilogue: v = acc + bias[n] + (bias2 && !zmask[m] ? bias2[n] : 0); relu opt.
// (if bias2==null && zmask!=null: zero row when zmask[m])
__global__ __launch_bounds__(256, 2) void mma_gemm(
    const __half* __restrict__ Ah, const __half* __restrict__ Al, int lda,
    const __half* __restrict__ Wh, int ldw,
    int Kd,
    const float* __restrict__ bias, const float* __restrict__ bias2,
    float* __restrict__ Cf, int ldcf,
    __half* __restrict__ Oh, __half* __restrict__ Ol, int ldo,
    const int* __restrict__ zmask, int flags)
{
    extern __shared__ __align__(16) char smem_raw[];
    uint32_t sb = (uint32_t)__cvta_generic_to_shared(smem_raw);
    int tid = threadIdx.x;
    int m0 = blockIdx.y * 128, n0 = blockIdx.x * 128;
    int lane = tid & 31, wid = tid >> 5;
    int wm = wid & 1, wn = wid >> 1;

    float d[4][4][4];
    #pragma unroll
    for (int i = 0; i < 4; i++)
        #pragma unroll
        for (int j = 0; j < 4; j++)
            #pragma unroll
            for (int r = 0; r < 4; r++) d[i][j][r] = 0.f;

    int row = tid >> 1;
    int ce  = (tid & 1) << 3;
    size_t ga0 = (size_t)(m0 + row) * lda + ce;
    size_t gw0 = (size_t)(n0 + row) * ldw + ce;
    uint32_t sw = sb + (uint32_t)(row * SMS + ce) * 2;

    int nch = Kd >> 5;
    issue_chunk(sw, 0, Ah, Al, ga0, Wh, gw0);
    if (nch > 1) issue_chunk(sw, STGB, Ah, Al, ga0 + 32, Wh, gw0 + 32);

    for (int c = 0; c < nch; c++) {
        if (c + 2 < nch) {
            int k0 = (c + 2) << 5;
            issue_chunk(sw, (uint32_t)((c + 2) % NSTG) * STGB, Ah, Al, ga0 + k0, Wh, gw0 + k0);
        }
        int issuedJ = (c + 2 < nch) ? c + 2 : nch - 1;
        int allow = issuedJ - c;
        if (allow >= 2)      asm volatile("cp.async.wait_group 2;\n" ::: "memory");
        else if (allow == 1) asm volatile("cp.async.wait_group 1;\n" ::: "memory");
        else                 asm volatile("cp.async.wait_group 0;\n" ::: "memory");
        __syncthreads();

        uint32_t base = sb + (uint32_t)(c % NSTG) * STGB;
        #pragma unroll
        for (int h = 0; h < 2; h++) {
            uint32_t ah[4][4], al[4][4], bh[2][4];
            int colA = (h << 4) + ((lane >> 4) << 3);
            #pragma unroll
            for (int mi = 0; mi < 4; mi++) {
                int r_ = wm * 64 + mi * 16 + (lane & 15);
                uint32_t ad = base + (uint32_t)(r_ * SMS + colA) * 2;
                ldm4(ah[mi], ad);
                ldm4(al[mi], ad + MATB);
            }
            #pragma unroll
            for (int nj2 = 0; nj2 < 2; nj2++) {
                int r_ = wn * 32 + nj2 * 16 + (lane & 7) + (((lane >> 3) & 1) << 3);
                uint32_t bd = base + 2 * MATB + (uint32_t)(r_ * SMS + colA) * 2;
                ldm4(bh[nj2], bd);
            }
            #pragma unroll
            for (int mi = 0; mi < 4; mi++)
                #pragma unroll
                for (int nj = 0; nj < 4; nj++)
                    mmaf16(d[mi][nj], ah[mi], bh[nj >> 1][nj & 1], bh[nj >> 1][(nj & 1) + 2]);
            #pragma unroll
            for (int mi = 0; mi < 4; mi++)
                #pragma unroll
                for (int nj = 0; nj < 4; nj++)
                    mmaf16(d[mi][nj], al[mi], bh[nj >> 1][nj & 1], bh[nj >> 1][(nj & 1) + 2]);
        }
        __syncthreads();
    }

    int gr = lane >> 2, tg = lane & 3;
    #pragma unroll
    for (int mi = 0; mi < 4; mi++) {
        int mb = m0 + wm * 64 + mi * 16 + gr;
        #pragma unroll
        for (int half = 0; half < 2; half++) {
            int m = mb + half * 8;
            bool zm = (zmask != nullptr) && (zmask[m] != 0);
            #pragma unroll
            for (int nj = 0; nj < 4; nj++) {
                int n = n0 + wn * 32 + nj * 8 + tg * 2;
                float v0 = d[mi][nj][half * 2 + 0];
                float v1 = d[mi][nj][half * 2 + 1];
                if (bias) { v0 += bias[n]; v1 += bias[n + 1]; }
                if (bias2) {
                    if (!zm) { v0 += bias2[n]; v1 += bias2[n + 1]; }
                } else if (zm) { v0 = 0.f; v1 = 0.f; }
                if (flags & GF_RELU) { v0 = fmaxf(v0, 0.f); v1 = fmaxf(v1, 0.f); }
                if (Cf) *(float2*)&Cf[(size_t)m * ldcf + n] = make_float2(v0, v1);
                if (Oh) {
                    __half2 hh, ll;
                    split2h(v0, hh.x, ll.x);
                    split2h(v1, hh.y, ll.y);
                    *(__half2*)&Oh[(size_t)m * ldo + n] = hh;
                    *(__half2*)&Ol[(size_t)m * ldo + n] = ll;
                }
            }
        }
    }
}

// ---------------- fused keyv-build + attention (4 warps, cos smem) ----------
// One warp per row m. Pass A: build keyv in fp32 (cos cached in smem), scores.
// Pass B: re-gather (L2-hot) + cos from smem, ctx accumulation.
// ctx zeroed for all-masked rows (o1-zeroing folded here).
__global__ __launch_bounds__(128) void fused_attn(
    const int* __restrict__ neigh,
    const int* __restrict__ eidx,
    const float* __restrict__ etime,
    const float* __restrict__ ts, int ts_div,
    const float* __restrict__ nf, const float* __restrict__ mem,
    const float* __restrict__ ef,
    const float* __restrict__ dense_neigh,
    const float* __restrict__ tw, const float* __restrict__ tb,
    const float* __restrict__ QW,
    const __half* __restrict__ bufh, const __half* __restrict__ bufl,
    const float* __restrict__ wqb, const float* __restrict__ cqb,
    __half* __restrict__ ctxh, __half* __restrict__ ctxl,
    int* __restrict__ inv, int M)
{
    __shared__ float s_tw[128], s_tb[128];
    __shared__ float cosb[4][N_K * 128];
    int tid = threadIdx.x;
    s_tw[tid] = tw[tid];
    s_tb[tid] = tb[tid];
    __syncthreads();

    int wl = tid >> 5, lane = tid & 31;
    int m = blockIdx.x * 4 + wl;
    if (m >= M) return;
    const float SC = 0.08838834764831843f;   // 1/sqrt(128)
    float* cb = cosb[wl];
    int jj = 2 * lane;

    // qb_h = src . wqb_h + cqb_h   (src = buf hi+lo cols 768..895)
    float qb0, qb1;
    {
        size_t sbse = (size_t)m * 896 + 768 + jj;
        float2 sh0 = __half22float2(*(const __half2*)&bufh[sbse]);
        float2 sl0 = __half22float2(*(const __half2*)&bufl[sbse]);
        float2 sh1 = __half22float2(*(const __half2*)&bufh[sbse + 64]);
        float2 sl1 = __half22float2(*(const __half2*)&bufl[sbse + 64]);
        float sx0 = sh0.x + sl0.x, sy0 = sh0.y + sl0.y;
        float sx1 = sh1.x + sl1.x, sy1 = sh1.y + sl1.y;
        float2 w00 = *(const float2*)&wqb[jj],       w01 = *(const float2*)&wqb[jj + 64];
        float2 w10 = *(const float2*)&wqb[128 + jj], w11 = *(const float2*)&wqb[128 + jj + 64];
        qb0 = sx0*w00.x + sy0*w00.y + sx1*w01.x + sy1*w01.y;
        qb1 = sx0*w10.x + sy0*w10.y + sx1*w11.x + sy1*w11.y;
        #pragma unroll
        for (int o = 16; o; o >>= 1) {
            qb0 += __shfl_xor_sync(0xffffffffu, qb0, o);
            qb1 += __shfl_xor_sync(0xffffffffu, qb1, o);
        }
        qb0 += cqb[0]; qb1 += cqb[1];
    }

    float2 qw0[6], qw1[6];
    {
        const float* qwp = QW + (size_t)m * 768;
        #pragma unroll
        for (int t = 0; t < 6; t++) {
            qw0[t] = *(const float2*)&qwp[jj + 64 * t];
            qw1[t] = *(const float2*)&qwp[384 + jj + 64 * t];
        }
    }

    float tsv = ts[m / ts_div];
    bool msk[N_K]; bool allm = true;
    int nd[N_K], ed[N_K];
    #pragma unroll
    for (int k = 0; k < N_K; k++) {
        nd[k] = neigh[m * N_K + k];
        ed[k] = eidx [m * N_K + k];
        msk[k] = (nd[k] == 0);
        allm = allm && msk[k];
    }

    // ---- pass A: scores (cos written to smem)
    float s0[N_K], s1[N_K];
    #pragma unroll
    for (int k = 0; k < N_K; k++) {
        float2 v[6];
        if (dense_neigh) {
            const float* dr = dense_neigh + (size_t)(m * N_K + k) * N_D;
            v[0] = *(const float2*)&dr[jj];
            v[1] = *(const float2*)&dr[jj + 64];
        } else {
            const float* nr = nf  + (size_t)nd[k] * N_D;
            const float* mr = mem + (size_t)nd[k] * N_D;
            float2 a0 = *(const float2*)&nr[jj],      b0 = *(const float2*)&mr[jj];
            float2 a1 = *(const float2*)&nr[jj + 64], b1 = *(const float2*)&mr[jj + 64];
            v[0] = make_float2(a0.x + b0.x, a0.y + b0.y);
            v[1] = make_float2(a1.x + b1.x, a1.y + b1.y);
        }
        {
            const float* er = ef + (size_t)ed[k] * N_D;
            v[2] = *(const float2*)&er[jj];
            v[3] = *(const float2*)&er[jj + 64];
        }
        float dd = tsv - etime[m * N_K + k];
        v[4].x = cosf(__fadd_rn(__fmul_rn(dd, s_tw[jj]),      s_tb[jj]));
        v[4].y = cosf(__fadd_rn(__fmul_rn(dd, s_tw[jj + 1]),  s_tb[jj + 1]));
        v[5].x = cosf(__fadd_rn(__fmul_rn(dd, s_tw[jj + 64]), s_tb[jj + 64]));
        v[5].y = cosf(__fadd_rn(__fmul_rn(dd, s_tw[jj + 65]), s_tb[jj + 65]));
        *(float2*)&cb[k * 128 + jj]      = v[4];
        *(float2*)&cb[k * 128 + jj + 64] = v[5];
        float p0 = 0.f, p1 = 0.f;
        #pragma unroll
        for (int t = 0; t < 6; t++) {
            p0 += qw0[t].x * v[t].x + qw0[t].y * v[t].y;
            p1 += qw1[t].x * v[t].x + qw1[t].y * v[t].y;
        }
        #pragma unroll
        for (int o = 16; o; o >>= 1) {
            p0 += __shfl_xor_sync(0xffffffffu, p0, o);
            p1 += __shfl_xor_sync(0xffffffffu, p1, o);
        }
        bool mk = msk[k] && !(allm && k == 0);
        s0[k] = mk ? -1e9f : (p0 + qb0) * SC;
        s1[k] = mk ? -1e9f : (p1 + qb1) * SC;
    }

    float mx0 = s0[0], mx1 = s1[0];
    #pragma unroll
    for (int k = 1; k < N_K; k++) { mx0 = fmaxf(mx0, s0[k]); mx1 = fmaxf(mx1, s1[k]); }
    float sm0 = 0.f, sm1 = 0.f;
    #pragma unroll
    for (int k = 0; k < N_K; k++) {
        s0[k] = expf(s0[k] - mx0); sm0 += s0[k];
        s1[k] = expf(s1[k] - mx1); sm1 += s1[k];
    }
    // fold invalid-row zeroing (o1 = 0) into ctx
    float zf = allm ? 0.f : 1.f;
    float r0 = zf / sm0, r1 = zf / sm1;

    // ---- pass B: ctx (gathers L2-hot; cos from smem)
    float2 a0[6], a1[6];
    #pragma unroll
    for (int t = 0; t < 6; t++) { a0[t] = make_float2(0.f, 0.f); a1[t] = make_float2(0.f, 0.f); }
    #pragma unroll
    for (int k = 0; k < N_K; k++) {
        float w0 = s0[k] * r0, w1 = s1[k] * r1;
        float2 v[6];
        if (dense_neigh) {
            const float* dr = dense_neigh + (size_t)(m * N_K + k) * N_D;
            v[0] = *(const float2*)&dr[jj];
            v[1] = *(const float2*)&dr[jj + 64];
        } else {
            const float* nr = nf  + (size_t)nd[k] * N_D;
            const float* mr = mem + (size_t)nd[k] * N_D;
            float2 c0 = *(const float2*)&nr[jj],      d0 = *(const float2*)&mr[jj];
            float2 c1 = *(const float2*)&nr[jj + 64], d1 = *(const float2*)&mr[jj + 64];
            v[0] = make_float2(c0.x + d0.x, c0.y + d0.y);
            v[1] = make_float2(c1.x + d1.x, c1.y + d1.y);
        }
        {
            const float* er = ef + (size_t)ed[k] * N_D;
            v[2] = *(const float2*)&er[jj];
            v[3] = *(const float2*)&er[jj + 64];
        }
        v[4] = *(const float2*)&cb[k * 128 + jj];
        v[5] = *(const float2*)&cb[k * 128 + jj + 64];
        #pragma unroll
        for (int t = 0; t < 6; t++) {
            a0[t].x = fmaf(w0, v[t].x, a0[t].x); a0[t].y = fmaf(w0, v[t].y, a0[t].y);
            a1[t].x = fmaf(w1, v[t].x, a1[t].x); a1[t].y = fmaf(w1, v[t].y, a1[t].y);
        }
    }

    size_t ob = (size_t)m * 896 + jj;
    #pragma unroll
    for (int t = 0; t < 6; t++) {
        __half2 hh, ll;
        split2h(a0[t].x, hh.x, ll.x); split2h(a0[t].y, hh.y, ll.y);
        *(__half2*)&ctxh[ob + 64 * t] = hh;
        *(__half2*)&ctxl[ob + 64 * t] = ll;
        split2h(a1[t].x, hh.x, ll.x); split2h(a1[t].y, hh.y, ll.y);
        *(__half2*)&ctxh[ob + 384 + 64 * t] = hh;
        *(__half2*)&ctxl[ob + 384 + 64 * t] = ll;
    }
    if (lane == 0) inv[m] = allm ? 1 : 0;
}

// ---------------- one temporal attention layer ------------------------------
struct Ptrs {
    __half *bufh, *bufl, *hh, *hl;
    float *QW; int* inv;
    __half *wcq, *wf, *w2;
    float *cq, *ckq, *cvec, *wqb, *cqb;
};

static void run_layer(const Ptrs& P, int p, int M,
                      const int* neigh, const float* dense_neigh,
                      const int* eidx, const float* etime,
                      const float* ts, int ts_div,
                      const float* nf, const float* mem, const float* ef,
                      const float* tw, const float* tb,
                      const float* b1, const float* b2,
                      float* outCf, __half* outOh, __half* outOl, int out_ldo)
{
    // QW = src @ Wcombq^T + ckq
    mma_gemm<<<dim3(6, M/128), 256, GSMEM>>>(
        P.bufh + 768, P.bufl + 768, 896,
        P.wcq + (size_t)p*768*128, 128, 128,
        P.ckq + p*768, nullptr, P.QW, 768, nullptr, nullptr, 0, nullptr, 0);
    // fused keyv-build + attention -> ctx into buf cols 0..767
    fused_attn<<<(M + 3) / 4, 128>>>(neigh, eidx, etime, ts, ts_div,
                                     nf, mem, ef, dense_neigh, tw, tb,
                                     P.QW, P.bufh, P.bufl,
                                     P.wqb + p*256, P.cqb + p*2,
                                     P.bufh, P.bufl, P.inv, M);
    // h = relu(buf @ wf^T + b1 + (valid ? cvec : 0))
    mma_gemm<<<dim3(1, M/128), 256, GSMEM>>>(
        P.bufh, P.bufl, 896,
        P.wf + (size_t)p*128*896, 896, 896,
        b1 + p*128, P.cvec + p*128, nullptr, 0, P.hh, P.hl, 128, P.inv, GF_RELU);
    // out = h @ W2^T + b2
    mma_gemm<<<dim3(1, M/128), 256, GSMEM>>>(
        P.hh, P.hl, 128,
        P.w2 + (size_t)p*16384, 128, 128,
        b2 + p*128, nullptr, outCf, 128, outOh, outOl, out_ldo, nullptr, 0);
}

// ---------------- entry -----------------------------------------------------
extern "C" void kernel_launch(void* const* d_in, const int* in_sizes, int n_in,
                              void* d_out, int out_size)
{
    const float* node_feat   = (const float*)d_in[0];
    const float* memory      = (const float*)d_in[1];
    const float* edge_feat   = (const float*)d_in[2];
    const float* time_w      = (const float*)d_in[3];
    const float* time_b      = (const float*)d_in[4];
    const float* Wq          = (const float*)d_in[5];
    const float* bq          = (const float*)d_in[6];
    const float* Wk          = (const float*)d_in[7];
    const float* bk          = (const float*)d_in[8];
    const float* Wv          = (const float*)d_in[9];
    const float* bv          = (const float*)d_in[10];
    const float* Wo          = (const float*)d_in[11];
    const float* bo          = (const float*)d_in[12];
    const float* W1          = (const float*)d_in[13];
    const float* b1          = (const float*)d_in[14];
    const float* W2          = (const float*)d_in[15];
    const float* b2          = (const float*)d_in[16];
    const float* timestamps  = (const float*)d_in[17];
    const int*   src_nodes   = (const int*)d_in[18];
    const int*   neighbors1  = (const int*)d_in[19];
    const int*   edge_idx1   = (const int*)d_in[20];
    const float* edge_times1 = (const float*)d_in[21];
    const int*   neighbors2  = (const int*)d_in[22];
    const int*   edge_idx2   = (const int*)d_in[23];
    const float* edge_times2 = (const float*)d_in[24];

    cudaFuncSetAttribute(mma_gemm, cudaFuncAttributeMaxDynamicSharedMemorySize, GSMEM);

    Ptrs P; float *NL1, *tmpvo, *bvo;
    cudaGetSymbolAddress((void**)&P.QW,   g_QW);
    cudaGetSymbolAddress((void**)&P.bufh, g_buf_h);
    cudaGetSymbolAddress((void**)&P.bufl, g_buf_l);
    cudaGetSymbolAddress((void**)&P.hh,   g_h_h);
    cudaGetSymbolAddress((void**)&P.hl,   g_h_l);
    cudaGetSymbolAddress((void**)&NL1,    g_NL1);
    cudaGetSymbolAddress((void**)&P.inv,  g_inv);
    cudaGetSymbolAddress((void**)&P.cq,   g_cq);
    cudaGetSymbolAddress((void**)&P.wcq,  g_wcq);
    cudaGetSymbolAddress((void**)&P.ckq,  g_ckq);
    cudaGetSymbolAddress((void**)&tmpvo,  g_tmpvo);
    cudaGetSymbolAddress((void**)&bvo,    g_bvo);
    cudaGetSymbolAddress((void**)&P.wf,   g_wf);
    cudaGetSymbolAddress((void**)&P.cvec, g_cvec);
    cudaGetSymbolAddress((void**)&P.w2,   g_w2);
    cudaGetSymbolAddress((void**)&P.wqb,  g_wqb);
    cudaGetSymbolAddress((void**)&P.cqb,  g_cqb);

    // weight prep
    const_q_kernel<<<2, 256>>>(Wq, bq, time_b, P.cq);
    comb_vo_kernel<<<dim3(256, 2), 768>>>(Wo, Wv, bo, bv, tmpvo, bvo);
    comb_q_kernel <<<dim3(768, 2), 128>>>(Wk, Wq, P.cq, P.wcq, P.ckq);
    comb_qb_kernel<<<dim3(2, 2),   128>>>(Wq, bk, P.cq, P.wqb, P.cqb);
    comb_w1_kernel<<<dim3(128, 2), 768>>>(W1, tmpvo, bvo, P.wf, P.cvec);
    prep_misc<<<(2*2*128*128 + 255)/256, 256>>>(W1, W2, P.wf, P.w2);

    // stage 1: layer-1 embedding of flattened first-hop neighbors (p0)
    gather_emb_kernel<<<M_HOP2, 128>>>(node_feat, memory, neighbors1, P.bufh, P.bufl, M_HOP2);
    run_layer(P, 0, M_HOP2, neighbors2, nullptr, edge_idx2, edge_times2,
              timestamps, N_K, node_feat, memory, edge_feat, time_w, time_b,
              b1, b2, NL1, nullptr, nullptr, 0);

    // stage 2: layer-1 embedding of src nodes (p0); SL1 -> buf col 768
    gather_emb_kernel<<<N_B, 128>>>(node_feat, memory, src_nodes, P.bufh, P.bufl, N_B);
    run_layer(P, 0, N_B, neighbors1, nullptr, edge_idx1, edge_times1,
              timestamps, 1, node_feat, memory, edge_feat, time_w, time_b,
              b1, b2, nullptr, P.bufh + 768, P.bufl + 768, 896);

    // stage 3: layer-2 aggregation (p1), neighbor feats = NL1
    run_layer(P, 1, N_B, neighbors1, NL1, edge_idx1, edge_times1,
              timestamps, 1, node_feat, memory, edge_feat, time_w, time_b,
              b1, b2, (float*)d_out, nullptr, nullptr, 0);
}